// round 2
// baseline (speedup 1.0000x reference)
#include <cuda_runtime.h>
#include <math.h>
#include <stdint.h>

// ---------------------------------------------------------------------------
// SSITrimLoss: masked scale/shift-invariant trimmed L1 loss.
// Pipeline (7 launches):
//   1. moments       : per-block partial masked moments (188 MB)
//   2. finalize      : alpha/beta/k per sample; zero hists
//   3. residual      : res=|a*p+b-g| store + 2048-bin count+sum hist (251 MB)
//   4. select0       : pick level-0 bin, rank-within, sum/count below bin
//   5. compact       : gather candidates of selected bin (63 MB, mostly L2)
//   6. finish        : per-sample 21-bit refine over candidates -> loss[b]
//   7. reduce        : mean over B -> out
// Selection is bit-exact (monotone uint encoding of non-negative floats).
// ---------------------------------------------------------------------------

#define BB    32
#define NMAX  491520
#define TPB   256
#define BLKX  32
#define BIGF  1e30f

__device__ __align__(16) float        g_res[(size_t)BB * NMAX];
__device__ __align__(16) unsigned int g_cand[(size_t)BB * NMAX];
__device__ float              g_part[BB][BLKX][5];
__device__ unsigned int       g_hcnt[BB][2048];
__device__ float              g_hsum[BB][2048];
__device__ float              g_alpha[BB], g_beta[BB];
__device__ int                g_k[BB];
__device__ long long          g_rank[BB];
__device__ int                g_sel0[BB];
__device__ double             g_sumbelow[BB];
__device__ long long          g_cntbelow[BB];
__device__ int                g_candcnt[BB];
__device__ float              g_loss[BB];

// ------------------------- warp reduce helpers -----------------------------
__device__ __forceinline__ float warp_sum(float v) {
    #pragma unroll
    for (int off = 16; off; off >>= 1) v += __shfl_down_sync(0xffffffffu, v, off);
    return v;
}
__device__ __forceinline__ double warp_sum_d(double v) {
    #pragma unroll
    for (int off = 16; off; off >>= 1) v += __shfl_down_sync(0xffffffffu, v, off);
    return v;
}
__device__ __forceinline__ long long warp_sum_ll(long long v) {
    #pragma unroll
    for (int off = 16; off; off >>= 1) v += __shfl_down_sync(0xffffffffu, v, off);
    return v;
}

// ------------------------------ 1. moments ---------------------------------
__global__ __launch_bounds__(TPB) void moments_kernel(
        const float* __restrict__ pred, const float* __restrict__ gt,
        const int* __restrict__ mask, int N) {
    int b = blockIdx.y;
    int n4 = N >> 2;
    const float4* p4 = reinterpret_cast<const float4*>(pred) + (size_t)b * n4;
    const float4* g4 = reinterpret_cast<const float4*>(gt)   + (size_t)b * n4;
    const int4*   m4 = reinterpret_cast<const int4*>(mask)   + (size_t)b * n4;

    float sn = 0.f, sp = 0.f, sg = 0.f, spp = 0.f, spg = 0.f;
    int stride = gridDim.x * blockDim.x;
    for (int i = blockIdx.x * blockDim.x + threadIdx.x; i < n4; i += stride) {
        float4 p = p4[i]; float4 g = g4[i]; int4 m = m4[i];
        float mf;
        mf = m.x > 0 ? 1.f : 0.f;
        sn += mf; sp += mf*p.x; sg += mf*g.x; spp += mf*p.x*p.x; spg += mf*p.x*g.x;
        mf = m.y > 0 ? 1.f : 0.f;
        sn += mf; sp += mf*p.y; sg += mf*g.y; spp += mf*p.y*p.y; spg += mf*p.y*g.y;
        mf = m.z > 0 ? 1.f : 0.f;
        sn += mf; sp += mf*p.z; sg += mf*g.z; spp += mf*p.z*p.z; spg += mf*p.z*g.z;
        mf = m.w > 0 ? 1.f : 0.f;
        sn += mf; sp += mf*p.w; sg += mf*g.w; spp += mf*p.w*p.w; spg += mf*p.w*g.w;
    }
    sn = warp_sum(sn); sp = warp_sum(sp); sg = warp_sum(sg);
    spp = warp_sum(spp); spg = warp_sum(spg);

    __shared__ float ws[5][8];
    int lane = threadIdx.x & 31, w = threadIdx.x >> 5;
    if (lane == 0) { ws[0][w]=sn; ws[1][w]=sp; ws[2][w]=sg; ws[3][w]=spp; ws[4][w]=spg; }
    __syncthreads();
    if (w == 0) {
        float a0 = lane < 8 ? ws[0][lane] : 0.f;
        float a1 = lane < 8 ? ws[1][lane] : 0.f;
        float a2 = lane < 8 ? ws[2][lane] : 0.f;
        float a3 = lane < 8 ? ws[3][lane] : 0.f;
        float a4 = lane < 8 ? ws[4][lane] : 0.f;
        a0 = warp_sum(a0); a1 = warp_sum(a1); a2 = warp_sum(a2);
        a3 = warp_sum(a3); a4 = warp_sum(a4);
        if (lane == 0) {
            g_part[b][blockIdx.x][0] = a0;
            g_part[b][blockIdx.x][1] = a1;
            g_part[b][blockIdx.x][2] = a2;
            g_part[b][blockIdx.x][3] = a3;
            g_part[b][blockIdx.x][4] = a4;
        }
    }
}

// ------------------------------ 2. finalize --------------------------------
__global__ void finalize_kernel() {
    int b = blockIdx.x;
    int tid = threadIdx.x;
    // zero histograms + candidate counter for this sample
    for (int i = tid; i < 2048; i += blockDim.x) {
        g_hcnt[b][i] = 0u;
        g_hsum[b][i] = 0.f;
    }
    if (tid == 0) g_candcnt[b] = 0;

    if (tid < 32) {
        double v0 = (double)g_part[b][tid][0];
        double v1 = (double)g_part[b][tid][1];
        double v2 = (double)g_part[b][tid][2];
        double v3 = (double)g_part[b][tid][3];
        double v4 = (double)g_part[b][tid][4];
        v0 = warp_sum_d(v0); v1 = warp_sum_d(v1); v2 = warp_sum_d(v2);
        v3 = warp_sum_d(v3); v4 = warp_sum_d(v4);
        if (tid == 0) {
            double n  = v0;
            double ns = n < 1.0 ? 1.0 : n;
            double md = v1 / ns, mz = v2 / ns;
            double var = v3 / ns - md * md;
            double cov = v4 / ns - md * mz;
            double alpha = cov / (var + 1e-6);
            double beta  = mz - alpha * md;
            g_alpha[b] = (float)alpha;
            g_beta[b]  = (float)beta;
            int k = (int)floorf(0.8f * (float)n);   // reference-matching f32 arith
            g_k[b] = k;
            g_rank[b] = (long long)k - 1;
        }
    }
}

// ------------------------------ 3. residual --------------------------------
__global__ __launch_bounds__(TPB) void residual_kernel(
        const float* __restrict__ pred, const float* __restrict__ gt,
        const int* __restrict__ mask, int N) {
    int b = blockIdx.y;
    __shared__ unsigned int scnt[2048];
    __shared__ float        ssum[2048];
    for (int i = threadIdx.x; i < 2048; i += blockDim.x) { scnt[i]=0u; ssum[i]=0.f; }
    __syncthreads();

    int n4 = N >> 2;
    const float4* p4 = reinterpret_cast<const float4*>(pred) + (size_t)b * n4;
    const float4* g4 = reinterpret_cast<const float4*>(gt)   + (size_t)b * n4;
    const int4*   m4 = reinterpret_cast<const int4*>(mask)   + (size_t)b * n4;
    float4*       r4 = reinterpret_cast<float4*>(g_res)      + (size_t)b * n4;

    float a = g_alpha[b], be = g_beta[b];
    int stride = gridDim.x * blockDim.x;
    for (int i = blockIdx.x * blockDim.x + threadIdx.x; i < n4; i += stride) {
        float4 p = p4[i]; float4 g = g4[i]; int4 m = m4[i];
        float4 r;
        r.x = (m.x > 0) ? fabsf(fmaf(a, p.x, be) - g.x) : BIGF;
        r.y = (m.y > 0) ? fabsf(fmaf(a, p.y, be) - g.y) : BIGF;
        r.z = (m.z > 0) ? fabsf(fmaf(a, p.z, be) - g.z) : BIGF;
        r.w = (m.w > 0) ? fabsf(fmaf(a, p.w, be) - g.w) : BIGF;
        r4[i] = r;
        // only valid pixels histogrammed (invalid all map to one bin -> skip)
        if (m.x > 0) { unsigned bin = __float_as_uint(r.x) >> 21;
                       atomicAdd(&scnt[bin], 1u); atomicAdd(&ssum[bin], r.x); }
        if (m.y > 0) { unsigned bin = __float_as_uint(r.y) >> 21;
                       atomicAdd(&scnt[bin], 1u); atomicAdd(&ssum[bin], r.y); }
        if (m.z > 0) { unsigned bin = __float_as_uint(r.z) >> 21;
                       atomicAdd(&scnt[bin], 1u); atomicAdd(&ssum[bin], r.z); }
        if (m.w > 0) { unsigned bin = __float_as_uint(r.w) >> 21;
                       atomicAdd(&scnt[bin], 1u); atomicAdd(&ssum[bin], r.w); }
    }
    __syncthreads();
    for (int i = threadIdx.x; i < 2048; i += blockDim.x) {
        unsigned c = scnt[i];
        if (c) {
            atomicAdd(&g_hcnt[b][i], c);
            atomicAdd(&g_hsum[b][i], ssum[i]);
        }
    }
}

// ------------------------------ 4. select0 ---------------------------------
__global__ void select0_kernel() {
    int b = blockIdx.x;
    int tid = threadIdx.x;
    long long r = g_rank[b];

    __shared__ long long tsum[TPB];
    __shared__ int s_bin;
    __shared__ long long s_before;
    __shared__ double sred[8];
    __shared__ long long credd[1];  // unused placeholder

    unsigned int c[8];
    long long mysum = 0;
    #pragma unroll
    for (int j = 0; j < 8; j++) { c[j] = g_hcnt[b][tid*8+j]; mysum += (long long)c[j]; }
    tsum[tid] = mysum;
    __syncthreads();
    for (int off = 1; off < TPB; off <<= 1) {
        long long v = (tid >= off) ? tsum[tid - off] : 0;
        __syncthreads();
        tsum[tid] += v;
        __syncthreads();
    }
    long long inc = tsum[tid];
    long long base = inc - mysum;
    if (tid == 0) s_bin = -1;
    __syncthreads();

    if (r >= 0 && r >= base && r < inc) {
        long long cum = base;
        #pragma unroll
        for (int j = 0; j < 8; j++) {
            if (r < cum + (long long)c[j]) { s_bin = tid*8+j; s_before = cum; break; }
            cum += (long long)c[j];
        }
    }
    __syncthreads();

    int selbin = s_bin;
    // sum of g_hsum over bins strictly below selected bin
    double mys = 0.0;
    if (selbin >= 0) {
        #pragma unroll
        for (int j = 0; j < 8; j++) {
            int idx = tid*8+j;
            if (idx < selbin) mys += (double)g_hsum[b][idx];
        }
    }
    mys = warp_sum_d(mys);
    int lane = tid & 31, w = tid >> 5;
    if (lane == 0) sred[w] = mys;
    __syncthreads();
    if (w == 0) {
        double v = lane < 8 ? sred[lane] : 0.0;
        v = warp_sum_d(v);
        if (lane == 0) {
            if (selbin >= 0) {
                g_sel0[b]     = selbin;
                g_rank[b]     = r - s_before;
                g_cntbelow[b] = s_before;
                g_sumbelow[b] = v;
            } else {
                g_sel0[b]     = -1;       // k == 0 case
                g_cntbelow[b] = 0;
                g_sumbelow[b] = 0.0;
            }
        }
    }
    (void)credd;
}

// ------------------------------ 5. compact ---------------------------------
__global__ __launch_bounds__(TPB) void compact_kernel(int N) {
    int b = blockIdx.y;
    int sel = g_sel0[b];
    int n4 = N >> 2;
    const uint4* r4 = reinterpret_cast<const uint4*>(g_res) + (size_t)b * n4;
    unsigned int* cand = g_cand + (size_t)b * NMAX;
    int lane = threadIdx.x & 31;

    int stride = gridDim.x * blockDim.x;
    // n4 divides evenly by grid stride -> warp stays converged
    for (int i = blockIdx.x * blockDim.x + threadIdx.x; i < n4; i += stride) {
        uint4 r = r4[i];
        #pragma unroll
        for (int j = 0; j < 4; j++) {
            unsigned bits = (j==0) ? r.x : (j==1) ? r.y : (j==2) ? r.z : r.w;
            bool match = ((int)(bits >> 21) == sel);
            unsigned bal = __ballot_sync(0xffffffffu, match);
            if (bal) {
                int leader = __ffs(bal) - 1;
                int pos = 0;
                if (lane == leader) pos = atomicAdd(&g_candcnt[b], __popc(bal));
                pos = __shfl_sync(0xffffffffu, pos, leader);
                pos += __popc(bal & ((1u << lane) - 1u));
                if (match) cand[pos] = bits;
            }
        }
    }
}

// ------------------------------ 6. finish ----------------------------------
#define FTPB 1024
__global__ __launch_bounds__(FTPB) void finish_kernel() {
    int b = blockIdx.x;
    int tid = threadIdx.x;
    int k = g_k[b];

    __shared__ unsigned int hist[2048];
    __shared__ long long tsum[FTPB];
    __shared__ int s_bin;
    __shared__ long long s_before;
    __shared__ double sred[32];
    __shared__ long long lred[32];

    if (k <= 0) { if (tid == 0) g_loss[b] = 0.f; return; }

    int m = g_candcnt[b];
    long long rw = g_rank[b];
    int sel0 = g_sel0[b];
    const unsigned int* cand = g_cand + (size_t)b * NMAX;

    // ---- pass A: bits[20:10], 2048 bins ----
    for (int i = tid; i < 2048; i += FTPB) hist[i] = 0u;
    __syncthreads();
    for (int i = tid; i < m; i += FTPB)
        atomicAdd(&hist[(cand[i] >> 10) & 2047u], 1u);
    __syncthreads();
    {
        unsigned c0 = hist[tid*2], c1 = hist[tid*2+1];
        long long mysum = (long long)c0 + c1;
        tsum[tid] = mysum;
        __syncthreads();
        for (int off = 1; off < FTPB; off <<= 1) {
            long long v = (tid >= off) ? tsum[tid - off] : 0;
            __syncthreads();
            tsum[tid] += v;
            __syncthreads();
        }
        long long inc = tsum[tid], base = inc - mysum;
        if (rw >= base && rw < inc) {
            if (rw < base + (long long)c0) { s_bin = tid*2;     s_before = base; }
            else                           { s_bin = tid*2 + 1; s_before = base + c0; }
        }
        __syncthreads();
    }
    int selA = s_bin;
    rw -= s_before;
    __syncthreads();

    // ---- pass B: bits[9:0], 1024 bins ----
    for (int i = tid; i < 2048; i += FTPB) hist[i] = 0u;
    __syncthreads();
    for (int i = tid; i < m; i += FTPB) {
        unsigned bits = cand[i];
        if (((bits >> 10) & 2047u) == (unsigned)selA)
            atomicAdd(&hist[bits & 1023u], 1u);
    }
    __syncthreads();
    {
        long long mysum = (tid < 1024) ? (long long)hist[tid] : 0;
        tsum[tid] = mysum;
        __syncthreads();
        for (int off = 1; off < FTPB; off <<= 1) {
            long long v = (tid >= off) ? tsum[tid - off] : 0;
            __syncthreads();
            tsum[tid] += v;
            __syncthreads();
        }
        long long inc = tsum[tid], base = inc - mysum;
        if (rw >= base && rw < inc) { s_bin = tid; }
        __syncthreads();
    }
    int selB = s_bin;
    unsigned v_bits = ((unsigned)sel0 << 21) | ((unsigned)selA << 10) | (unsigned)selB;
    float v = __uint_as_float(v_bits);

    // ---- pass C: sum/count of candidates strictly below v ----
    double s = 0.0;
    long long c = 0;
    for (int i = tid; i < m; i += FTPB) {
        unsigned bits = cand[i];
        if (bits < v_bits) { s += (double)__uint_as_float(bits); c++; }
    }
    s = warp_sum_d(s);
    c = warp_sum_ll(c);
    int lane = tid & 31, w = tid >> 5;
    if (lane == 0) { sred[w] = s; lred[w] = c; }
    __syncthreads();
    if (w == 0) {
        double sv = sred[lane];
        long long cv = lred[lane];
        sv = warp_sum_d(sv);
        cv = warp_sum_ll(cv);
        if (lane == 0) {
            long long total_less = g_cntbelow[b] + cv;
            double kept = g_sumbelow[b] + sv +
                          (double)((long long)k - total_less) * (double)v;
            g_loss[b] = (float)(kept / (double)k);
        }
    }
}

// ------------------------------ 7. reduce ----------------------------------
__global__ void reduce_kernel(float* out) {
    int b = threadIdx.x;
    float loss = (b < BB) ? g_loss[b] : 0.f;
    #pragma unroll
    for (int off = 16; off; off >>= 1) loss += __shfl_down_sync(0xffffffffu, loss, off);
    if (b == 0) out[0] = loss / (float)BB;
}

// ------------------------------ launch -------------------------------------
extern "C" void kernel_launch(void* const* d_in, const int* in_sizes, int n_in,
                              void* d_out, int out_size) {
    const float* pred = (const float*)d_in[0];
    const float* gt   = (const float*)d_in[1];
    const int*   mask = (const int*)d_in[2];
    float* out = (float*)d_out;

    int total = in_sizes[0];
    int N = total / BB;

    dim3 grid(BLKX, BB);

    moments_kernel<<<grid, TPB>>>(pred, gt, mask, N);
    finalize_kernel<<<BB, TPB>>>();
    residual_kernel<<<grid, TPB>>>(pred, gt, mask, N);
    select0_kernel<<<BB, TPB>>>();
    compact_kernel<<<grid, TPB>>>(N);
    finish_kernel<<<BB, FTPB>>>();
    reduce_kernel<<<1, 32>>>(out);
}

// round 3
// speedup vs baseline: 1.0519x; 1.0519x over previous
#include <cuda_runtime.h>
#include <math.h>
#include <stdint.h>

// ---------------------------------------------------------------------------
// SSITrimLoss: masked scale/shift-invariant trimmed L1 loss.
// Pipeline (7 launches), NO float atomics anywhere:
//   1. moments   : per-block partial masked moments (188 MB)
//   2. finalize  : alpha/beta/k per sample; zero hists
//   3. residual  : res=|a*p+b-g| store + 2048-bin COUNT hist, valid px only
//   4. select0   : pick level-0 bin + rank-within (counts only)
//   5. compact   : one sweep of res: sum/count strictly below bin (registers),
//                  gather in-bin elements as candidates
//   6. finish    : per-sample 21-bit refine over candidates -> loss[b]
//   7. reduce    : mean over B -> out
// Selection is bit-exact (monotone uint encoding of non-negative floats).
// ---------------------------------------------------------------------------

#define BB    32
#define NMAX  491520
#define TPB   256
#define BLKX  32
#define BIGF  1e30f

__device__ __align__(16) float        g_res[(size_t)BB * NMAX];
__device__ __align__(16) unsigned int g_cand[(size_t)BB * NMAX];
__device__ float              g_part[BB][BLKX][5];
__device__ unsigned int       g_hcnt[BB][2048];
__device__ float              g_alpha[BB], g_beta[BB];
__device__ int                g_k[BB];
__device__ long long          g_rank[BB];
__device__ int                g_sel0[BB];
__device__ double             g_sumbelow[BB];
__device__ unsigned long long g_cntbelow[BB];
__device__ int                g_candcnt[BB];
__device__ float              g_loss[BB];

// ------------------------- warp reduce helpers -----------------------------
__device__ __forceinline__ float warp_sum(float v) {
    #pragma unroll
    for (int off = 16; off; off >>= 1) v += __shfl_down_sync(0xffffffffu, v, off);
    return v;
}
__device__ __forceinline__ double warp_sum_d(double v) {
    #pragma unroll
    for (int off = 16; off; off >>= 1) v += __shfl_down_sync(0xffffffffu, v, off);
    return v;
}
__device__ __forceinline__ long long warp_sum_ll(long long v) {
    #pragma unroll
    for (int off = 16; off; off >>= 1) v += __shfl_down_sync(0xffffffffu, v, off);
    return v;
}

// ------------------------------ 1. moments ---------------------------------
__global__ __launch_bounds__(TPB) void moments_kernel(
        const float* __restrict__ pred, const float* __restrict__ gt,
        const int* __restrict__ mask, int N) {
    int b = blockIdx.y;
    int n4 = N >> 2;
    const float4* p4 = reinterpret_cast<const float4*>(pred) + (size_t)b * n4;
    const float4* g4 = reinterpret_cast<const float4*>(gt)   + (size_t)b * n4;
    const int4*   m4 = reinterpret_cast<const int4*>(mask)   + (size_t)b * n4;

    float sn = 0.f, sp = 0.f, sg = 0.f, spp = 0.f, spg = 0.f;
    int stride = gridDim.x * blockDim.x;
    for (int i = blockIdx.x * blockDim.x + threadIdx.x; i < n4; i += stride) {
        float4 p = p4[i]; float4 g = g4[i]; int4 m = m4[i];
        float mf;
        mf = m.x > 0 ? 1.f : 0.f;
        sn += mf; sp += mf*p.x; sg += mf*g.x; spp += mf*p.x*p.x; spg += mf*p.x*g.x;
        mf = m.y > 0 ? 1.f : 0.f;
        sn += mf; sp += mf*p.y; sg += mf*g.y; spp += mf*p.y*p.y; spg += mf*p.y*g.y;
        mf = m.z > 0 ? 1.f : 0.f;
        sn += mf; sp += mf*p.z; sg += mf*g.z; spp += mf*p.z*p.z; spg += mf*p.z*g.z;
        mf = m.w > 0 ? 1.f : 0.f;
        sn += mf; sp += mf*p.w; sg += mf*g.w; spp += mf*p.w*p.w; spg += mf*p.w*g.w;
    }
    sn = warp_sum(sn); sp = warp_sum(sp); sg = warp_sum(sg);
    spp = warp_sum(spp); spg = warp_sum(spg);

    __shared__ float ws[5][8];
    int lane = threadIdx.x & 31, w = threadIdx.x >> 5;
    if (lane == 0) { ws[0][w]=sn; ws[1][w]=sp; ws[2][w]=sg; ws[3][w]=spp; ws[4][w]=spg; }
    __syncthreads();
    if (w == 0) {
        float a0 = lane < 8 ? ws[0][lane] : 0.f;
        float a1 = lane < 8 ? ws[1][lane] : 0.f;
        float a2 = lane < 8 ? ws[2][lane] : 0.f;
        float a3 = lane < 8 ? ws[3][lane] : 0.f;
        float a4 = lane < 8 ? ws[4][lane] : 0.f;
        a0 = warp_sum(a0); a1 = warp_sum(a1); a2 = warp_sum(a2);
        a3 = warp_sum(a3); a4 = warp_sum(a4);
        if (lane == 0) {
            g_part[b][blockIdx.x][0] = a0;
            g_part[b][blockIdx.x][1] = a1;
            g_part[b][blockIdx.x][2] = a2;
            g_part[b][blockIdx.x][3] = a3;
            g_part[b][blockIdx.x][4] = a4;
        }
    }
}

// ------------------------------ 2. finalize --------------------------------
__global__ void finalize_kernel() {
    int b = blockIdx.x;
    int tid = threadIdx.x;
    for (int i = tid; i < 2048; i += blockDim.x) g_hcnt[b][i] = 0u;
    if (tid == 0) {
        g_candcnt[b] = 0;
        g_sumbelow[b] = 0.0;
        g_cntbelow[b] = 0ull;
    }

    if (tid < 32) {
        double v0 = (double)g_part[b][tid][0];
        double v1 = (double)g_part[b][tid][1];
        double v2 = (double)g_part[b][tid][2];
        double v3 = (double)g_part[b][tid][3];
        double v4 = (double)g_part[b][tid][4];
        v0 = warp_sum_d(v0); v1 = warp_sum_d(v1); v2 = warp_sum_d(v2);
        v3 = warp_sum_d(v3); v4 = warp_sum_d(v4);
        if (tid == 0) {
            double n  = v0;
            double ns = n < 1.0 ? 1.0 : n;
            double md = v1 / ns, mz = v2 / ns;
            double var = v3 / ns - md * md;
            double cov = v4 / ns - md * mz;
            double alpha = cov / (var + 1e-6);
            double beta  = mz - alpha * md;
            g_alpha[b] = (float)alpha;
            g_beta[b]  = (float)beta;
            int k = (int)floorf(0.8f * (float)n);   // reference-matching f32 arith
            g_k[b] = k;
            g_rank[b] = (long long)k - 1;
        }
    }
}

// ------------------------------ 3. residual --------------------------------
__global__ __launch_bounds__(TPB) void residual_kernel(
        const float* __restrict__ pred, const float* __restrict__ gt,
        const int* __restrict__ mask, int N) {
    int b = blockIdx.y;
    __shared__ unsigned int scnt[2048];
    for (int i = threadIdx.x; i < 2048; i += blockDim.x) scnt[i] = 0u;
    __syncthreads();

    int n4 = N >> 2;
    const float4* p4 = reinterpret_cast<const float4*>(pred) + (size_t)b * n4;
    const float4* g4 = reinterpret_cast<const float4*>(gt)   + (size_t)b * n4;
    const int4*   m4 = reinterpret_cast<const int4*>(mask)   + (size_t)b * n4;
    float4*       r4 = reinterpret_cast<float4*>(g_res)      + (size_t)b * n4;

    float a = g_alpha[b], be = g_beta[b];
    int stride = gridDim.x * blockDim.x;
    for (int i = blockIdx.x * blockDim.x + threadIdx.x; i < n4; i += stride) {
        float4 p = p4[i]; float4 g = g4[i]; int4 m = m4[i];
        float4 r;
        r.x = (m.x > 0) ? fabsf(fmaf(a, p.x, be) - g.x) : BIGF;
        r.y = (m.y > 0) ? fabsf(fmaf(a, p.y, be) - g.y) : BIGF;
        r.z = (m.z > 0) ? fabsf(fmaf(a, p.z, be) - g.z) : BIGF;
        r.w = (m.w > 0) ? fabsf(fmaf(a, p.w, be) - g.w) : BIGF;
        r4[i] = r;
        if (m.x > 0) atomicAdd(&scnt[__float_as_uint(r.x) >> 21], 1u);
        if (m.y > 0) atomicAdd(&scnt[__float_as_uint(r.y) >> 21], 1u);
        if (m.z > 0) atomicAdd(&scnt[__float_as_uint(r.z) >> 21], 1u);
        if (m.w > 0) atomicAdd(&scnt[__float_as_uint(r.w) >> 21], 1u);
    }
    __syncthreads();
    for (int i = threadIdx.x; i < 2048; i += blockDim.x) {
        unsigned c = scnt[i];
        if (c) atomicAdd(&g_hcnt[b][i], c);
    }
}

// ------------------------------ 4. select0 ---------------------------------
__global__ void select0_kernel() {
    int b = blockIdx.x;
    int tid = threadIdx.x;
    long long r = g_rank[b];

    __shared__ long long tsum[TPB];
    __shared__ int s_bin;
    __shared__ long long s_before;

    unsigned int c[8];
    long long mysum = 0;
    #pragma unroll
    for (int j = 0; j < 8; j++) { c[j] = g_hcnt[b][tid*8+j]; mysum += (long long)c[j]; }
    tsum[tid] = mysum;
    __syncthreads();
    for (int off = 1; off < TPB; off <<= 1) {
        long long v = (tid >= off) ? tsum[tid - off] : 0;
        __syncthreads();
        tsum[tid] += v;
        __syncthreads();
    }
    long long inc = tsum[tid];
    long long base = inc - mysum;
    if (tid == 0) s_bin = -1;
    __syncthreads();

    if (r >= 0 && r >= base && r < inc) {
        long long cum = base;
        #pragma unroll
        for (int j = 0; j < 8; j++) {
            if (r < cum + (long long)c[j]) { s_bin = tid*8+j; s_before = cum; break; }
            cum += (long long)c[j];
        }
    }
    __syncthreads();
    if (tid == 0) {
        if (s_bin >= 0) {
            g_sel0[b] = s_bin;
            g_rank[b] = r - s_before;
        } else {
            g_sel0[b] = -1;    // k == 0 case
        }
    }
}

// ------------------------------ 5. compact ---------------------------------
// One sweep of res: per-thread register sum/count of elements strictly below
// the selected level-0 bin; warp-aggregated gather of in-bin candidates.
__global__ __launch_bounds__(TPB) void compact_kernel(int N) {
    int b = blockIdx.y;
    int sel = g_sel0[b];
    int n4 = N >> 2;
    const uint4* r4 = reinterpret_cast<const uint4*>(g_res) + (size_t)b * n4;
    unsigned int* cand = g_cand + (size_t)b * NMAX;
    int lane = threadIdx.x & 31;
    unsigned selu = (unsigned)sel;          // sel==-1 -> huge, never matches

    float sbelow = 0.f;
    int   cbelow = 0;

    int stride = gridDim.x * blockDim.x;
    // n4 divides evenly by grid stride -> warp stays converged
    for (int i = blockIdx.x * blockDim.x + threadIdx.x; i < n4; i += stride) {
        uint4 r = r4[i];
        #pragma unroll
        for (int j = 0; j < 4; j++) {
            unsigned bits = (j==0) ? r.x : (j==1) ? r.y : (j==2) ? r.z : r.w;
            unsigned top = bits >> 21;
            if (top < selu) { sbelow += __uint_as_float(bits); cbelow++; }
            bool match = (top == selu);
            unsigned bal = __ballot_sync(0xffffffffu, match);
            if (bal) {
                int leader = __ffs(bal) - 1;
                int pos = 0;
                if (lane == leader) pos = atomicAdd(&g_candcnt[b], __popc(bal));
                pos = __shfl_sync(0xffffffffu, pos, leader);
                pos += __popc(bal & ((1u << lane) - 1u));
                if (match) cand[pos] = bits;
            }
        }
    }

    // block-reduce sum/count of below-bin elements
    sbelow = warp_sum(sbelow);
    long long cb = warp_sum_ll((long long)cbelow);
    __shared__ float  ws[8];
    __shared__ long long wc[8];
    int w = threadIdx.x >> 5;
    if (lane == 0) { ws[w] = sbelow; wc[w] = cb; }
    __syncthreads();
    if (w == 0) {
        float a0 = lane < 8 ? ws[lane] : 0.f;
        long long b0 = lane < 8 ? wc[lane] : 0;
        a0 = warp_sum(a0);
        b0 = warp_sum_ll(b0);
        if (lane == 0 && (a0 != 0.f || b0 != 0)) {
            atomicAdd(&g_sumbelow[b], (double)a0);
            atomicAdd(&g_cntbelow[b], (unsigned long long)b0);
        }
    }
}

// ------------------------------ 6. finish ----------------------------------
#define FTPB 1024
__global__ __launch_bounds__(FTPB) void finish_kernel() {
    int b = blockIdx.x;
    int tid = threadIdx.x;
    int k = g_k[b];

    __shared__ unsigned int hist[2048];
    __shared__ long long tsum[FTPB];
    __shared__ int s_bin;
    __shared__ long long s_before;
    __shared__ double sred[32];
    __shared__ long long lred[32];

    if (k <= 0) { if (tid == 0) g_loss[b] = 0.f; return; }

    int m = g_candcnt[b];
    long long rw = g_rank[b];
    int sel0 = g_sel0[b];
    const unsigned int* cand = g_cand + (size_t)b * NMAX;

    // ---- pass A: bits[20:10], 2048 bins ----
    for (int i = tid; i < 2048; i += FTPB) hist[i] = 0u;
    __syncthreads();
    for (int i = tid; i < m; i += FTPB)
        atomicAdd(&hist[(cand[i] >> 10) & 2047u], 1u);
    __syncthreads();
    {
        unsigned c0 = hist[tid*2], c1 = hist[tid*2+1];
        long long mysum = (long long)c0 + c1;
        tsum[tid] = mysum;
        __syncthreads();
        for (int off = 1; off < FTPB; off <<= 1) {
            long long v = (tid >= off) ? tsum[tid - off] : 0;
            __syncthreads();
            tsum[tid] += v;
            __syncthreads();
        }
        long long inc = tsum[tid], base = inc - mysum;
        if (rw >= base && rw < inc) {
            if (rw < base + (long long)c0) { s_bin = tid*2;     s_before = base; }
            else                           { s_bin = tid*2 + 1; s_before = base + c0; }
        }
        __syncthreads();
    }
    int selA = s_bin;
    rw -= s_before;
    __syncthreads();

    // ---- pass B: bits[9:0], 1024 bins ----
    for (int i = tid; i < 2048; i += FTPB) hist[i] = 0u;
    __syncthreads();
    for (int i = tid; i < m; i += FTPB) {
        unsigned bits = cand[i];
        if (((bits >> 10) & 2047u) == (unsigned)selA)
            atomicAdd(&hist[bits & 1023u], 1u);
    }
    __syncthreads();
    {
        long long mysum = (tid < 1024) ? (long long)hist[tid] : 0;
        tsum[tid] = mysum;
        __syncthreads();
        for (int off = 1; off < FTPB; off <<= 1) {
            long long v = (tid >= off) ? tsum[tid - off] : 0;
            __syncthreads();
            tsum[tid] += v;
            __syncthreads();
        }
        long long inc = tsum[tid], base = inc - mysum;
        if (rw >= base && rw < inc) { s_bin = tid; }
        __syncthreads();
    }
    int selB = s_bin;
    unsigned v_bits = ((unsigned)sel0 << 21) | ((unsigned)selA << 10) | (unsigned)selB;
    float v = __uint_as_float(v_bits);

    // ---- pass C: sum/count of candidates strictly below v ----
    double s = 0.0;
    long long c = 0;
    for (int i = tid; i < m; i += FTPB) {
        unsigned bits = cand[i];
        if (bits < v_bits) { s += (double)__uint_as_float(bits); c++; }
    }
    s = warp_sum_d(s);
    c = warp_sum_ll(c);
    int lane = tid & 31, w = tid >> 5;
    if (lane == 0) { sred[w] = s; lred[w] = c; }
    __syncthreads();
    if (w == 0) {
        double sv = sred[lane];
        long long cv = lred[lane];
        sv = warp_sum_d(sv);
        cv = warp_sum_ll(cv);
        if (lane == 0) {
            long long total_less = (long long)g_cntbelow[b] + cv;
            double kept = g_sumbelow[b] + sv +
                          (double)((long long)k - total_less) * (double)v;
            g_loss[b] = (float)(kept / (double)k);
        }
    }
}

// ------------------------------ 7. reduce ----------------------------------
__global__ void reduce_kernel(float* out) {
    int b = threadIdx.x;
    float loss = (b < BB) ? g_loss[b] : 0.f;
    #pragma unroll
    for (int off = 16; off; off >>= 1) loss += __shfl_down_sync(0xffffffffu, loss, off);
    if (b == 0) out[0] = loss / (float)BB;
}

// ------------------------------ launch -------------------------------------
extern "C" void kernel_launch(void* const* d_in, const int* in_sizes, int n_in,
                              void* d_out, int out_size) {
    const float* pred = (const float*)d_in[0];
    const float* gt   = (const float*)d_in[1];
    const int*   mask = (const int*)d_in[2];
    float* out = (float*)d_out;

    int total = in_sizes[0];
    int N = total / BB;

    dim3 grid(BLKX, BB);

    moments_kernel<<<grid, TPB>>>(pred, gt, mask, N);
    finalize_kernel<<<BB, TPB>>>();
    residual_kernel<<<grid, TPB>>>(pred, gt, mask, N);
    select0_kernel<<<BB, TPB>>>();
    compact_kernel<<<grid, TPB>>>(N);
    finish_kernel<<<BB, FTPB>>>();
    reduce_kernel<<<1, 32>>>(out);
}

// round 4
// speedup vs baseline: 2.6802x; 2.5480x over previous
#include <cuda_runtime.h>
#include <math.h>
#include <stdint.h>

// ---------------------------------------------------------------------------
// SSITrimLoss: masked scale/shift-invariant trimmed L1 loss.
// Pipeline (7 launches), no float atomics, no same-address atomic storms:
//   1. moments   : per-block partial masked moments (188 MB)
//   2. finalize  : alpha/beta/k per sample; zero hists
//   3. residual  : res=|a*p+b-g| store + 2048-bin COUNT hist, valid px only
//   4. select0   : pick level-0 bin + rank-within (counts only)
//   5. compact   : two-pass per-block: count+below-sums, reserve once, gather
//   6. finish    : per-sample 21-bit refine over candidates -> loss[b]
//   7. reduce    : mean over B -> out
// Selection is bit-exact (monotone uint encoding of non-negative floats).
// ---------------------------------------------------------------------------

#define BB    32
#define NMAX  491520
#define TPB   256
#define BLKX  32
#define BIGF  1e30f

__device__ __align__(16) float        g_res[(size_t)BB * NMAX];
__device__ __align__(16) unsigned int g_cand[(size_t)BB * NMAX];
__device__ float              g_part[BB][BLKX][5];
__device__ unsigned int       g_hcnt[BB][2048];
__device__ float              g_alpha[BB], g_beta[BB];
__device__ int                g_k[BB];
__device__ long long          g_rank[BB];
__device__ int                g_sel0[BB];
__device__ double             g_sumbelow[BB];
__device__ unsigned long long g_cntbelow[BB];
__device__ int                g_candcnt[BB];
__device__ float              g_loss[BB];

// ------------------------- warp reduce helpers -----------------------------
__device__ __forceinline__ float warp_sum(float v) {
    #pragma unroll
    for (int off = 16; off; off >>= 1) v += __shfl_down_sync(0xffffffffu, v, off);
    return v;
}
__device__ __forceinline__ double warp_sum_d(double v) {
    #pragma unroll
    for (int off = 16; off; off >>= 1) v += __shfl_down_sync(0xffffffffu, v, off);
    return v;
}
__device__ __forceinline__ long long warp_sum_ll(long long v) {
    #pragma unroll
    for (int off = 16; off; off >>= 1) v += __shfl_down_sync(0xffffffffu, v, off);
    return v;
}
__device__ __forceinline__ int warp_sum_i(int v) {
    #pragma unroll
    for (int off = 16; off; off >>= 1) v += __shfl_down_sync(0xffffffffu, v, off);
    return v;
}

// ------------------------------ 1. moments ---------------------------------
__global__ __launch_bounds__(TPB) void moments_kernel(
        const float* __restrict__ pred, const float* __restrict__ gt,
        const int* __restrict__ mask, int N) {
    int b = blockIdx.y;
    int n4 = N >> 2;
    const float4* p4 = reinterpret_cast<const float4*>(pred) + (size_t)b * n4;
    const float4* g4 = reinterpret_cast<const float4*>(gt)   + (size_t)b * n4;
    const int4*   m4 = reinterpret_cast<const int4*>(mask)   + (size_t)b * n4;

    float sn = 0.f, sp = 0.f, sg = 0.f, spp = 0.f, spg = 0.f;
    int stride = gridDim.x * blockDim.x;
    for (int i = blockIdx.x * blockDim.x + threadIdx.x; i < n4; i += stride) {
        float4 p = p4[i]; float4 g = g4[i]; int4 m = m4[i];
        float mf;
        mf = m.x > 0 ? 1.f : 0.f;
        sn += mf; sp += mf*p.x; sg += mf*g.x; spp += mf*p.x*p.x; spg += mf*p.x*g.x;
        mf = m.y > 0 ? 1.f : 0.f;
        sn += mf; sp += mf*p.y; sg += mf*g.y; spp += mf*p.y*p.y; spg += mf*p.y*g.y;
        mf = m.z > 0 ? 1.f : 0.f;
        sn += mf; sp += mf*p.z; sg += mf*g.z; spp += mf*p.z*p.z; spg += mf*p.z*g.z;
        mf = m.w > 0 ? 1.f : 0.f;
        sn += mf; sp += mf*p.w; sg += mf*g.w; spp += mf*p.w*p.w; spg += mf*p.w*g.w;
    }
    sn = warp_sum(sn); sp = warp_sum(sp); sg = warp_sum(sg);
    spp = warp_sum(spp); spg = warp_sum(spg);

    __shared__ float ws[5][8];
    int lane = threadIdx.x & 31, w = threadIdx.x >> 5;
    if (lane == 0) { ws[0][w]=sn; ws[1][w]=sp; ws[2][w]=sg; ws[3][w]=spp; ws[4][w]=spg; }
    __syncthreads();
    if (w == 0) {
        float a0 = lane < 8 ? ws[0][lane] : 0.f;
        float a1 = lane < 8 ? ws[1][lane] : 0.f;
        float a2 = lane < 8 ? ws[2][lane] : 0.f;
        float a3 = lane < 8 ? ws[3][lane] : 0.f;
        float a4 = lane < 8 ? ws[4][lane] : 0.f;
        a0 = warp_sum(a0); a1 = warp_sum(a1); a2 = warp_sum(a2);
        a3 = warp_sum(a3); a4 = warp_sum(a4);
        if (lane == 0) {
            g_part[b][blockIdx.x][0] = a0;
            g_part[b][blockIdx.x][1] = a1;
            g_part[b][blockIdx.x][2] = a2;
            g_part[b][blockIdx.x][3] = a3;
            g_part[b][blockIdx.x][4] = a4;
        }
    }
}

// ------------------------------ 2. finalize --------------------------------
__global__ void finalize_kernel() {
    int b = blockIdx.x;
    int tid = threadIdx.x;
    for (int i = tid; i < 2048; i += blockDim.x) g_hcnt[b][i] = 0u;
    if (tid == 0) {
        g_candcnt[b] = 0;
        g_sumbelow[b] = 0.0;
        g_cntbelow[b] = 0ull;
    }

    if (tid < 32) {
        double v0 = (double)g_part[b][tid][0];
        double v1 = (double)g_part[b][tid][1];
        double v2 = (double)g_part[b][tid][2];
        double v3 = (double)g_part[b][tid][3];
        double v4 = (double)g_part[b][tid][4];
        v0 = warp_sum_d(v0); v1 = warp_sum_d(v1); v2 = warp_sum_d(v2);
        v3 = warp_sum_d(v3); v4 = warp_sum_d(v4);
        if (tid == 0) {
            double n  = v0;
            double ns = n < 1.0 ? 1.0 : n;
            double md = v1 / ns, mz = v2 / ns;
            double var = v3 / ns - md * md;
            double cov = v4 / ns - md * mz;
            double alpha = cov / (var + 1e-6);
            double beta  = mz - alpha * md;
            g_alpha[b] = (float)alpha;
            g_beta[b]  = (float)beta;
            int k = (int)floorf(0.8f * (float)n);   // reference-matching f32 arith
            g_k[b] = k;
            g_rank[b] = (long long)k - 1;
        }
    }
}

// ------------------------------ 3. residual --------------------------------
__global__ __launch_bounds__(TPB) void residual_kernel(
        const float* __restrict__ pred, const float* __restrict__ gt,
        const int* __restrict__ mask, int N) {
    int b = blockIdx.y;
    __shared__ unsigned int scnt[2048];
    for (int i = threadIdx.x; i < 2048; i += blockDim.x) scnt[i] = 0u;
    __syncthreads();

    int n4 = N >> 2;
    const float4* p4 = reinterpret_cast<const float4*>(pred) + (size_t)b * n4;
    const float4* g4 = reinterpret_cast<const float4*>(gt)   + (size_t)b * n4;
    const int4*   m4 = reinterpret_cast<const int4*>(mask)   + (size_t)b * n4;
    float4*       r4 = reinterpret_cast<float4*>(g_res)      + (size_t)b * n4;

    float a = g_alpha[b], be = g_beta[b];
    int stride = gridDim.x * blockDim.x;
    for (int i = blockIdx.x * blockDim.x + threadIdx.x; i < n4; i += stride) {
        float4 p = p4[i]; float4 g = g4[i]; int4 m = m4[i];
        float4 r;
        r.x = (m.x > 0) ? fabsf(fmaf(a, p.x, be) - g.x) : BIGF;
        r.y = (m.y > 0) ? fabsf(fmaf(a, p.y, be) - g.y) : BIGF;
        r.z = (m.z > 0) ? fabsf(fmaf(a, p.z, be) - g.z) : BIGF;
        r.w = (m.w > 0) ? fabsf(fmaf(a, p.w, be) - g.w) : BIGF;
        r4[i] = r;
        if (m.x > 0) atomicAdd(&scnt[__float_as_uint(r.x) >> 21], 1u);
        if (m.y > 0) atomicAdd(&scnt[__float_as_uint(r.y) >> 21], 1u);
        if (m.z > 0) atomicAdd(&scnt[__float_as_uint(r.z) >> 21], 1u);
        if (m.w > 0) atomicAdd(&scnt[__float_as_uint(r.w) >> 21], 1u);
    }
    __syncthreads();
    for (int i = threadIdx.x; i < 2048; i += blockDim.x) {
        unsigned c = scnt[i];
        if (c) atomicAdd(&g_hcnt[b][i], c);
    }
}

// ------------------------------ 4. select0 ---------------------------------
__global__ void select0_kernel() {
    int b = blockIdx.x;
    int tid = threadIdx.x;
    long long r = g_rank[b];

    __shared__ long long tsum[TPB];
    __shared__ int s_bin;
    __shared__ long long s_before;

    unsigned int c[8];
    long long mysum = 0;
    #pragma unroll
    for (int j = 0; j < 8; j++) { c[j] = g_hcnt[b][tid*8+j]; mysum += (long long)c[j]; }
    tsum[tid] = mysum;
    __syncthreads();
    for (int off = 1; off < TPB; off <<= 1) {
        long long v = (tid >= off) ? tsum[tid - off] : 0;
        __syncthreads();
        tsum[tid] += v;
        __syncthreads();
    }
    long long inc = tsum[tid];
    long long base = inc - mysum;
    if (tid == 0) s_bin = -1;
    __syncthreads();

    if (r >= 0 && r >= base && r < inc) {
        long long cum = base;
        #pragma unroll
        for (int j = 0; j < 8; j++) {
            if (r < cum + (long long)c[j]) { s_bin = tid*8+j; s_before = cum; break; }
            cum += (long long)c[j];
        }
    }
    __syncthreads();
    if (tid == 0) {
        if (s_bin >= 0) {
            g_sel0[b] = s_bin;
            g_rank[b] = r - s_before;
        } else {
            g_sel0[b] = -1;    // k == 0 case
        }
    }
}

// ------------------------------ 5. compact ---------------------------------
// Two-pass per-block: pass 1 counts in-bin matches and accumulates sum/count
// of elements strictly below the bin. ONE global atomic per block reserves a
// contiguous range; pass 2 re-reads the (L1/L2-hot) chunk and gathers via a
// combined shared atomic. Avoids the same-address global-atomic storm.
__global__ __launch_bounds__(TPB) void compact_kernel(int N) {
    int b = blockIdx.y;
    unsigned selu = (unsigned)g_sel0[b];   // -1 -> huge, never matches
    int n4 = N >> 2;
    int chunk = n4 / gridDim.x;
    int start = blockIdx.x * chunk;
    int end   = (blockIdx.x == gridDim.x - 1) ? n4 : (start + chunk);
    const uint4* r4 = reinterpret_cast<const uint4*>(g_res) + (size_t)b * n4;
    unsigned int* cand = g_cand + (size_t)b * NMAX;

    float sbelow = 0.f;
    int   cbelow = 0;
    int   cmatch = 0;

    // ---- pass 1: count + below-bin sums ----
    for (int i = start + threadIdx.x; i < end; i += TPB) {
        uint4 r = r4[i];
        #pragma unroll
        for (int j = 0; j < 4; j++) {
            unsigned bits = (j==0) ? r.x : (j==1) ? r.y : (j==2) ? r.z : r.w;
            unsigned top = bits >> 21;
            if (top < selu) { sbelow += __uint_as_float(bits); cbelow++; }
            else if (top == selu) cmatch++;
        }
    }

    __shared__ float  wsum[8];
    __shared__ int    wcntb[8];
    __shared__ int    wcntm[8];
    __shared__ int    s_base;
    __shared__ int    s_local;
    int lane = threadIdx.x & 31, w = threadIdx.x >> 5;

    float sb = warp_sum(sbelow);
    int   cb = warp_sum_i(cbelow);
    int   cm = warp_sum_i(cmatch);
    if (lane == 0) { wsum[w] = sb; wcntb[w] = cb; wcntm[w] = cm; }
    __syncthreads();
    if (w == 0) {
        float a0 = lane < 8 ? wsum[lane]  : 0.f;
        int   b0 = lane < 8 ? wcntb[lane] : 0;
        int   c0 = lane < 8 ? wcntm[lane] : 0;
        a0 = warp_sum(a0);
        b0 = warp_sum_i(b0);
        c0 = warp_sum_i(c0);
        if (lane == 0) {
            s_local = 0;
            s_base = (c0 > 0) ? atomicAdd(&g_candcnt[b], c0) : 0;
            if (b0 > 0) {
                atomicAdd(&g_sumbelow[b], (double)a0);
                atomicAdd(&g_cntbelow[b], (unsigned long long)b0);
            }
        }
    }
    __syncthreads();
    int base = s_base;

    // ---- pass 2: gather matches (chunk is L1/L2-hot from pass 1) ----
    for (int i = start + threadIdx.x; i < end; i += TPB) {
        uint4 r = r4[i];
        #pragma unroll
        for (int j = 0; j < 4; j++) {
            unsigned bits = (j==0) ? r.x : (j==1) ? r.y : (j==2) ? r.z : r.w;
            if ((bits >> 21) == selu) {
                int p = atomicAdd(&s_local, 1);
                cand[base + p] = bits;
            }
        }
    }
}

// ------------------------------ 6. finish ----------------------------------
#define FTPB 1024
__global__ __launch_bounds__(FTPB) void finish_kernel() {
    int b = blockIdx.x;
    int tid = threadIdx.x;
    int k = g_k[b];

    __shared__ unsigned int hist[2048];
    __shared__ long long tsum[FTPB];
    __shared__ int s_bin;
    __shared__ long long s_before;
    __shared__ double sred[32];
    __shared__ long long lred[32];

    if (k <= 0) { if (tid == 0) g_loss[b] = 0.f; return; }

    int m = g_candcnt[b];
    long long rw = g_rank[b];
    int sel0 = g_sel0[b];
    const unsigned int* cand = g_cand + (size_t)b * NMAX;

    // ---- pass A: bits[20:10], 2048 bins ----
    for (int i = tid; i < 2048; i += FTPB) hist[i] = 0u;
    __syncthreads();
    for (int i = tid; i < m; i += FTPB)
        atomicAdd(&hist[(cand[i] >> 10) & 2047u], 1u);
    __syncthreads();
    {
        unsigned c0 = hist[tid*2], c1 = hist[tid*2+1];
        long long mysum = (long long)c0 + c1;
        tsum[tid] = mysum;
        __syncthreads();
        for (int off = 1; off < FTPB; off <<= 1) {
            long long v = (tid >= off) ? tsum[tid - off] : 0;
            __syncthreads();
            tsum[tid] += v;
            __syncthreads();
        }
        long long inc = tsum[tid], base = inc - mysum;
        if (rw >= base && rw < inc) {
            if (rw < base + (long long)c0) { s_bin = tid*2;     s_before = base; }
            else                           { s_bin = tid*2 + 1; s_before = base + c0; }
        }
        __syncthreads();
    }
    int selA = s_bin;
    rw -= s_before;
    __syncthreads();

    // ---- pass B: bits[9:0], 1024 bins ----
    for (int i = tid; i < 2048; i += FTPB) hist[i] = 0u;
    __syncthreads();
    for (int i = tid; i < m; i += FTPB) {
        unsigned bits = cand[i];
        if (((bits >> 10) & 2047u) == (unsigned)selA)
            atomicAdd(&hist[bits & 1023u], 1u);
    }
    __syncthreads();
    {
        long long mysum = (tid < 1024) ? (long long)hist[tid] : 0;
        tsum[tid] = mysum;
        __syncthreads();
        for (int off = 1; off < FTPB; off <<= 1) {
            long long v = (tid >= off) ? tsum[tid - off] : 0;
            __syncthreads();
            tsum[tid] += v;
            __syncthreads();
        }
        long long inc = tsum[tid], base = inc - mysum;
        if (rw >= base && rw < inc) { s_bin = tid; }
        __syncthreads();
    }
    int selB = s_bin;
    unsigned v_bits = ((unsigned)sel0 << 21) | ((unsigned)selA << 10) | (unsigned)selB;
    float v = __uint_as_float(v_bits);

    // ---- pass C: sum/count of candidates strictly below v ----
    double s = 0.0;
    long long c = 0;
    for (int i = tid; i < m; i += FTPB) {
        unsigned bits = cand[i];
        if (bits < v_bits) { s += (double)__uint_as_float(bits); c++; }
    }
    s = warp_sum_d(s);
    c = warp_sum_ll(c);
    int lane = tid & 31, w = tid >> 5;
    if (lane == 0) { sred[w] = s; lred[w] = c; }
    __syncthreads();
    if (w == 0) {
        double sv = sred[lane];
        long long cv = lred[lane];
        sv = warp_sum_d(sv);
        cv = warp_sum_ll(cv);
        if (lane == 0) {
            long long total_less = (long long)g_cntbelow[b] + cv;
            double kept = g_sumbelow[b] + sv +
                          (double)((long long)k - total_less) * (double)v;
            g_loss[b] = (float)(kept / (double)k);
        }
    }
}

// ------------------------------ 7. reduce ----------------------------------
__global__ void reduce_kernel(float* out) {
    int b = threadIdx.x;
    float loss = (b < BB) ? g_loss[b] : 0.f;
    #pragma unroll
    for (int off = 16; off; off >>= 1) loss += __shfl_down_sync(0xffffffffu, loss, off);
    if (b == 0) out[0] = loss / (float)BB;
}

// ------------------------------ launch -------------------------------------
extern "C" void kernel_launch(void* const* d_in, const int* in_sizes, int n_in,
                              void* d_out, int out_size) {
    const float* pred = (const float*)d_in[0];
    const float* gt   = (const float*)d_in[1];
    const int*   mask = (const int*)d_in[2];
    float* out = (float*)d_out;

    int total = in_sizes[0];
    int N = total / BB;

    dim3 grid(BLKX, BB);

    moments_kernel<<<grid, TPB>>>(pred, gt, mask, N);
    finalize_kernel<<<BB, TPB>>>();
    residual_kernel<<<grid, TPB>>>(pred, gt, mask, N);
    select0_kernel<<<BB, TPB>>>();
    compact_kernel<<<grid, TPB>>>(N);
    finish_kernel<<<BB, FTPB>>>();
    reduce_kernel<<<1, 32>>>(out);
}

// round 5
// speedup vs baseline: 2.8851x; 1.0765x over previous
#include <cuda_runtime.h>
#include <math.h>
#include <stdint.h>

// ---------------------------------------------------------------------------
// SSITrimLoss: masked scale/shift-invariant trimmed L1 loss.
// Pipeline (7 launches):
//   1. pack      : moments + compact valid (p,g) pairs per block segment
//                  (reads 188MB, writes ~63MB; invalid pixels never touched again)
//   2. finalize  : alpha/beta/k per sample; zero hists
//   3. hist      : res=|a*p+b-g| from pairs, 2048-bin count hist (63MB read)
//   4. select0   : pick level-0 bin + rank-within (hierarchical scan)
//   5. compact   : pairs again (L2-hot): below-bin sum/count + gather in-bin
//   6. finish    : per-sample 21-bit refine over candidates -> loss[b]
//   7. reduce    : mean over B -> out
// Selection is bit-exact (monotone uint encoding of non-negative floats).
// ---------------------------------------------------------------------------

#define BB    32
#define NMAX  491520
#define TPB   256
#define BLKX  32
#define FULLM 0xffffffffu

__device__ __align__(16) float2       g_pair[(size_t)BB * NMAX];  // valid pairs
__device__ __align__(16) unsigned int g_cand[(size_t)BB * NMAX];
__device__ float              g_part[BB][BLKX][5];
__device__ int                g_segcnt[BB][BLKX];
__device__ unsigned int       g_hcnt[BB][2048];
__device__ float              g_alpha[BB], g_beta[BB];
__device__ int                g_k[BB];
__device__ long long          g_rank[BB];
__device__ int                g_sel0[BB];
__device__ double             g_sumbelow[BB];
__device__ unsigned long long g_cntbelow[BB];
__device__ int                g_candcnt[BB];
__device__ float              g_loss[BB];

// ------------------------- warp reduce/scan helpers ------------------------
__device__ __forceinline__ float warp_sum(float v) {
    #pragma unroll
    for (int off = 16; off; off >>= 1) v += __shfl_down_sync(FULLM, v, off);
    return v;
}
__device__ __forceinline__ double warp_sum_d(double v) {
    #pragma unroll
    for (int off = 16; off; off >>= 1) v += __shfl_down_sync(FULLM, v, off);
    return v;
}
__device__ __forceinline__ long long warp_sum_ll(long long v) {
    #pragma unroll
    for (int off = 16; off; off >>= 1) v += __shfl_down_sync(FULLM, v, off);
    return v;
}
__device__ __forceinline__ int warp_sum_i(int v) {
    #pragma unroll
    for (int off = 16; off; off >>= 1) v += __shfl_down_sync(FULLM, v, off);
    return v;
}
__device__ __forceinline__ int warp_scan_incl(int v, int lane) {
    #pragma unroll
    for (int off = 1; off < 32; off <<= 1) {
        int t = __shfl_up_sync(FULLM, v, off);
        if (lane >= off) v += t;
    }
    return v;
}

// ------------------------ 1. pack (moments + gather) -----------------------
__global__ __launch_bounds__(TPB) void pack_kernel(
        const float* __restrict__ pred, const float* __restrict__ gt,
        const int* __restrict__ mask, int N) {
    int b = blockIdx.y;
    int n4 = N >> 2;
    int chunk4 = n4 / BLKX;                      // 3840
    int start = blockIdx.x * chunk4;
    int end   = (blockIdx.x == BLKX - 1) ? n4 : start + chunk4;

    const float4* p4 = reinterpret_cast<const float4*>(pred) + (size_t)b * n4;
    const float4* g4 = reinterpret_cast<const float4*>(gt)   + (size_t)b * n4;
    const int4*   m4 = reinterpret_cast<const int4*>(mask)   + (size_t)b * n4;
    float2* out = g_pair + (size_t)b * NMAX + (size_t)blockIdx.x * (chunk4 << 2);

    __shared__ int s_cnt;
    if (threadIdx.x == 0) s_cnt = 0;
    __syncthreads();

    int lane = threadIdx.x & 31;
    unsigned lmask = (1u << lane) - 1u;
    float sn = 0.f, sp = 0.f, sg = 0.f, spp = 0.f, spg = 0.f;

    for (int i = start + threadIdx.x; i < end; i += TPB) {
        float4 p = p4[i]; float4 g = g4[i]; int4 m = m4[i];
        #pragma unroll
        for (int j = 0; j < 4; j++) {
            float pv = (j==0)?p.x:(j==1)?p.y:(j==2)?p.z:p.w;
            float gv = (j==0)?g.x:(j==1)?g.y:(j==2)?g.z:g.w;
            int   mv = (j==0)?m.x:(j==1)?m.y:(j==2)?m.z:m.w;
            bool valid = mv > 0;
            if (valid) {
                sn += 1.f; sp += pv; sg += gv; spp += pv*pv; spg += pv*gv;
            }
            unsigned bal = __ballot_sync(FULLM, valid);
            int cnt = __popc(bal);
            int pos = 0;
            if (lane == 0 && cnt) pos = atomicAdd(&s_cnt, cnt);
            pos = __shfl_sync(FULLM, pos, 0);
            if (valid) out[pos + __popc(bal & lmask)] = make_float2(pv, gv);
        }
    }

    // block reduce moments
    sn = warp_sum(sn); sp = warp_sum(sp); sg = warp_sum(sg);
    spp = warp_sum(spp); spg = warp_sum(spg);
    __shared__ float ws[5][8];
    int w = threadIdx.x >> 5;
    if (lane == 0) { ws[0][w]=sn; ws[1][w]=sp; ws[2][w]=sg; ws[3][w]=spp; ws[4][w]=spg; }
    __syncthreads();
    if (w == 0) {
        float a0 = lane < 8 ? ws[0][lane] : 0.f;
        float a1 = lane < 8 ? ws[1][lane] : 0.f;
        float a2 = lane < 8 ? ws[2][lane] : 0.f;
        float a3 = lane < 8 ? ws[3][lane] : 0.f;
        float a4 = lane < 8 ? ws[4][lane] : 0.f;
        a0 = warp_sum(a0); a1 = warp_sum(a1); a2 = warp_sum(a2);
        a3 = warp_sum(a3); a4 = warp_sum(a4);
        if (lane == 0) {
            g_part[b][blockIdx.x][0] = a0;
            g_part[b][blockIdx.x][1] = a1;
            g_part[b][blockIdx.x][2] = a2;
            g_part[b][blockIdx.x][3] = a3;
            g_part[b][blockIdx.x][4] = a4;
            g_segcnt[b][blockIdx.x] = s_cnt;   // s_cnt final: lane0 wrote after all atomics? no!
        }
    }
}

// NOTE: s_cnt is finalized only after the loop; the write above happens after
// __syncthreads() which follows the loop, so s_cnt is complete. (atomics all
// issued before the first __syncthreads after the loop.)

// ------------------------------ 2. finalize --------------------------------
__global__ void finalize_kernel() {
    int b = blockIdx.x;
    int tid = threadIdx.x;
    for (int i = tid; i < 2048; i += blockDim.x) g_hcnt[b][i] = 0u;
    if (tid == 0) {
        g_candcnt[b] = 0;
        g_sumbelow[b] = 0.0;
        g_cntbelow[b] = 0ull;
    }
    if (tid < 32) {
        double v0 = (double)g_part[b][tid][0];
        double v1 = (double)g_part[b][tid][1];
        double v2 = (double)g_part[b][tid][2];
        double v3 = (double)g_part[b][tid][3];
        double v4 = (double)g_part[b][tid][4];
        v0 = warp_sum_d(v0); v1 = warp_sum_d(v1); v2 = warp_sum_d(v2);
        v3 = warp_sum_d(v3); v4 = warp_sum_d(v4);
        if (tid == 0) {
            double n  = v0;
            double ns = n < 1.0 ? 1.0 : n;
            double md = v1 / ns, mz = v2 / ns;
            double var = v3 / ns - md * md;
            double cov = v4 / ns - md * mz;
            double alpha = cov / (var + 1e-6);
            double beta  = mz - alpha * md;
            g_alpha[b] = (float)alpha;
            g_beta[b]  = (float)beta;
            int k = (int)floorf(0.8f * (float)n);   // reference-matching f32 arith
            g_k[b] = k;
            g_rank[b] = (long long)k - 1;
        }
    }
}

// ------------------------------ 3. hist ------------------------------------
__global__ __launch_bounds__(TPB) void hist_kernel(int N) {
    int b = blockIdx.y;
    int n4 = N >> 2;
    int chunk4 = n4 / BLKX;
    int cnt = g_segcnt[b][blockIdx.x];
    const float2* in = g_pair + (size_t)b * NMAX + (size_t)blockIdx.x * (chunk4 << 2);
    float a = g_alpha[b], be = g_beta[b];

    __shared__ unsigned int sh[2048];
    for (int i = threadIdx.x; i < 2048; i += TPB) sh[i] = 0u;
    __syncthreads();

    for (int i = threadIdx.x; i < cnt; i += TPB) {
        float2 pg = in[i];
        float r = fabsf(fmaf(a, pg.x, be) - pg.y);
        atomicAdd(&sh[__float_as_uint(r) >> 21], 1u);
    }
    __syncthreads();
    for (int i = threadIdx.x; i < 2048; i += TPB) {
        unsigned c = sh[i];
        if (c) atomicAdd(&g_hcnt[b][i], c);
    }
}

// ------------------------------ 4. select0 ---------------------------------
__global__ void select0_kernel() {
    int b = blockIdx.x;
    int tid = threadIdx.x;
    int lane = tid & 31, w = tid >> 5;
    long long r = g_rank[b];

    __shared__ int wtot[8];
    __shared__ int s_bin;
    __shared__ long long s_before;
    if (tid == 0) s_bin = -1;

    unsigned int c[8];
    int mysum = 0;
    #pragma unroll
    for (int j = 0; j < 8; j++) { c[j] = g_hcnt[b][tid*8+j]; mysum += (int)c[j]; }
    int incl = warp_scan_incl(mysum, lane);
    if (lane == 31) wtot[w] = incl;
    __syncthreads();
    int wbase = 0;
    #pragma unroll
    for (int j = 0; j < 8; j++) wbase += (j < w) ? wtot[j] : 0;
    long long base = (long long)wbase + incl - mysum;

    if (r >= base && r < base + mysum) {
        long long cum = base;
        #pragma unroll
        for (int j = 0; j < 8; j++) {
            if (r < cum + (long long)c[j]) { s_bin = tid*8+j; s_before = cum; break; }
            cum += (long long)c[j];
        }
    }
    __syncthreads();
    if (tid == 0) {
        if (s_bin >= 0) {
            g_sel0[b] = s_bin;
            g_rank[b] = r - s_before;
        } else {
            g_sel0[b] = -1;    // k == 0 case
        }
    }
}

// ------------------------------ 5. compact ---------------------------------
__global__ __launch_bounds__(TPB) void compact_kernel(int N) {
    int b = blockIdx.y;
    int n4 = N >> 2;
    int chunk4 = n4 / BLKX;
    int cnt = g_segcnt[b][blockIdx.x];
    const float2* in = g_pair + (size_t)b * NMAX + (size_t)blockIdx.x * (chunk4 << 2);
    unsigned int* cand = g_cand + (size_t)b * NMAX;
    float a = g_alpha[b], be = g_beta[b];
    unsigned selu = (unsigned)g_sel0[b];      // -1 -> huge, never matches

    float sbelow = 0.f;
    int   cbelow = 0, cmatch = 0;

    // pass 1: counts + below-bin sums
    for (int i = threadIdx.x; i < cnt; i += TPB) {
        float2 pg = in[i];
        float r = fabsf(fmaf(a, pg.x, be) - pg.y);
        unsigned top = __float_as_uint(r) >> 21;
        if (top < selu) { sbelow += r; cbelow++; }
        else if (top == selu) cmatch++;
    }

    __shared__ float wsum[8];
    __shared__ int   wcb[8], wcm[8];
    __shared__ int   s_base, s_local;
    int lane = threadIdx.x & 31, w = threadIdx.x >> 5;
    float sb = warp_sum(sbelow);
    int   cb = warp_sum_i(cbelow);
    int   cm = warp_sum_i(cmatch);
    if (lane == 0) { wsum[w] = sb; wcb[w] = cb; wcm[w] = cm; }
    __syncthreads();
    if (w == 0) {
        float a0 = lane < 8 ? wsum[lane] : 0.f;
        int   b0 = lane < 8 ? wcb[lane] : 0;
        int   c0 = lane < 8 ? wcm[lane] : 0;
        a0 = warp_sum(a0); b0 = warp_sum_i(b0); c0 = warp_sum_i(c0);
        if (lane == 0) {
            s_local = 0;
            s_base = (c0 > 0) ? atomicAdd(&g_candcnt[b], c0) : 0;
            if (b0 > 0) {
                atomicAdd(&g_sumbelow[b], (double)a0);
                atomicAdd(&g_cntbelow[b], (unsigned long long)b0);
            }
        }
    }
    __syncthreads();
    int base = s_base;

    // pass 2: gather in-bin candidates (segment is L1-hot from pass 1)
    for (int i = threadIdx.x; i < cnt; i += TPB) {
        float2 pg = in[i];
        float r = fabsf(fmaf(a, pg.x, be) - pg.y);
        unsigned bits = __float_as_uint(r);
        if ((bits >> 21) == selu) {
            int p = atomicAdd(&s_local, 1);
            cand[base + p] = bits;
        }
    }
}

// ------------------------------ 6. finish ----------------------------------
#define FTPB 1024
__global__ __launch_bounds__(FTPB) void finish_kernel() {
    int b = blockIdx.x;
    int tid = threadIdx.x;
    int lane = tid & 31, w = tid >> 5;
    int k = g_k[b];

    __shared__ unsigned int hist[2048];
    __shared__ int wtot[32];
    __shared__ int s_bin;
    __shared__ long long s_before;
    __shared__ double sred[32];
    __shared__ long long lred[32];

    if (k <= 0) { if (tid == 0) g_loss[b] = 0.f; return; }

    int m = g_candcnt[b];
    long long rw = g_rank[b];
    int sel0 = g_sel0[b];
    const unsigned int* cand = g_cand + (size_t)b * NMAX;

    // ---- pass A: bits[20:10], 2048 bins ----
    for (int i = tid; i < 2048; i += FTPB) hist[i] = 0u;
    __syncthreads();
    for (int i = tid; i < m; i += FTPB)
        atomicAdd(&hist[(cand[i] >> 10) & 2047u], 1u);
    __syncthreads();
    {
        int c0 = (int)hist[tid*2], c1 = (int)hist[tid*2+1];
        int mysum = c0 + c1;
        int incl = warp_scan_incl(mysum, lane);
        if (lane == 31) wtot[w] = incl;
        __syncthreads();
        int wbase = 0;
        for (int j = 0; j < w; j++) wbase += wtot[j];
        long long base = (long long)wbase + incl - mysum;
        if (rw >= base && rw < base + mysum) {
            if (rw < base + c0) { s_bin = tid*2;   s_before = base; }
            else                { s_bin = tid*2+1; s_before = base + c0; }
        }
        __syncthreads();
    }
    int selA = s_bin;
    rw -= s_before;
    __syncthreads();

    // ---- pass B: bits[9:0], 1024 bins ----
    for (int i = tid; i < 1024; i += FTPB) hist[i] = 0u;
    __syncthreads();
    for (int i = tid; i < m; i += FTPB) {
        unsigned bits = cand[i];
        if (((bits >> 10) & 2047u) == (unsigned)selA)
            atomicAdd(&hist[bits & 1023u], 1u);
    }
    __syncthreads();
    {
        int mysum = (int)hist[tid & 1023];   // tid<1024 anyway with FTPB=1024
        int incl = warp_scan_incl(mysum, lane);
        if (lane == 31) wtot[w] = incl;
        __syncthreads();
        int wbase = 0;
        for (int j = 0; j < w; j++) wbase += wtot[j];
        long long base = (long long)wbase + incl - mysum;
        if (rw >= base && rw < base + mysum) s_bin = tid;
        __syncthreads();
    }
    int selB = s_bin;
    unsigned v_bits = ((unsigned)sel0 << 21) | ((unsigned)selA << 10) | (unsigned)selB;
    float v = __uint_as_float(v_bits);

    // ---- pass C: sum/count of candidates strictly below v ----
    double s = 0.0;
    long long c = 0;
    for (int i = tid; i < m; i += FTPB) {
        unsigned bits = cand[i];
        if (bits < v_bits) { s += (double)__uint_as_float(bits); c++; }
    }
    s = warp_sum_d(s);
    c = warp_sum_ll(c);
    if (lane == 0) { sred[w] = s; lred[w] = c; }
    __syncthreads();
    if (w == 0) {
        double sv = sred[lane];
        long long cv = lred[lane];
        sv = warp_sum_d(sv);
        cv = warp_sum_ll(cv);
        if (lane == 0) {
            long long total_less = (long long)g_cntbelow[b] + cv;
            double kept = g_sumbelow[b] + sv +
                          (double)((long long)k - total_less) * (double)v;
            g_loss[b] = (float)(kept / (double)k);
        }
    }
}

// ------------------------------ 7. reduce ----------------------------------
__global__ void reduce_kernel(float* out) {
    int b = threadIdx.x;
    float loss = (b < BB) ? g_loss[b] : 0.f;
    #pragma unroll
    for (int off = 16; off; off >>= 1) loss += __shfl_down_sync(FULLM, loss, off);
    if (b == 0) out[0] = loss / (float)BB;
}

// ------------------------------ launch -------------------------------------
extern "C" void kernel_launch(void* const* d_in, const int* in_sizes, int n_in,
                              void* d_out, int out_size) {
    const float* pred = (const float*)d_in[0];
    const float* gt   = (const float*)d_in[1];
    const int*   mask = (const int*)d_in[2];
    float* out = (float*)d_out;

    int total = in_sizes[0];
    int N = total / BB;

    dim3 grid(BLKX, BB);

    pack_kernel<<<grid, TPB>>>(pred, gt, mask, N);
    finalize_kernel<<<BB, TPB>>>();
    hist_kernel<<<grid, TPB>>>(N);
    select0_kernel<<<BB, TPB>>>();
    compact_kernel<<<grid, TPB>>>(N);
    finish_kernel<<<BB, FTPB>>>();
    reduce_kernel<<<1, 32>>>(out);
}